// round 1
// baseline (speedup 1.0000x reference)
#include <cuda_runtime.h>
#include <cstdint>

// newIF spiking neuron: T=8 timestep IF recurrence + compensation rescale.
// x: [T*B, C, H, W] float32 viewed as [T, N] with N = B*C*H*W neurons.
// For each neuron:
//   mem = 0.5*thre
//   for t: mem += x[t]; spike[t] = (mem >= thre); mem -= spike[t]*thre
//   compen = min(mem - 0.5*thre + count*thre, T*thre)
//   new_thre = (compen > 0 && count > 0) ? compen / count : 0
//   out[t] = spike[t] * new_thre
//
// Purely HBM-bound: 256 MB in + 256 MB out. Strategy: float4 per thread,
// batch all 8 temporal loads up front (MLP=8), recurrence in registers,
// spikes as bitmasks, 8 coalesced float4 stores.

static constexpr int T_STEPS = 8;

__global__ __launch_bounds__(256)
void newif_kernel(const float4* __restrict__ x,
                  const float*  __restrict__ thresh,
                  float4* __restrict__ out,
                  int n4)  // N/4 = number of float4 lanes per timestep
{
    int i = blockIdx.x * blockDim.x + threadIdx.x;
    if (i >= n4) return;

    const float thre      = __ldg(thresh);
    const float half_thre = 0.5f * thre;
    const float cap       = (float)T_STEPS * thre;

    // Front-batch all temporal loads: independent addresses -> MLP=8.
    float4 xv[T_STEPS];
#pragma unroll
    for (int t = 0; t < T_STEPS; ++t) {
        xv[t] = x[(size_t)t * (size_t)n4 + (size_t)i];
    }

    float mem[4];
    int   cnt[4];
    unsigned msk[4];
#pragma unroll
    for (int l = 0; l < 4; ++l) { mem[l] = half_thre; cnt[l] = 0; msk[l] = 0u; }

    // IF recurrence, spikes recorded as bits.
#pragma unroll
    for (int t = 0; t < T_STEPS; ++t) {
        const float* xt = reinterpret_cast<const float*>(&xv[t]);
#pragma unroll
        for (int l = 0; l < 4; ++l) {
            float m = mem[l] + xt[l];
            bool s = (m >= thre);          // zif(mem - thre): heaviside at 0
            if (s) { m -= thre; cnt[l]++; msk[l] |= (1u << t); }
            mem[l] = m;
        }
    }

    // Per-neuron effective threshold.
    float nt[4];
#pragma unroll
    for (int l = 0; l < 4; ++l) {
        float compen = mem[l] - half_thre + (float)cnt[l] * thre;
        compen = fminf(compen, cap);
        bool cond = (compen > 0.0f) && (cnt[l] > 0);
        nt[l] = cond ? (compen / (float)cnt[l]) : 0.0f;
    }

    // Rescale spikes and store (coalesced float4 per timestep).
#pragma unroll
    for (int t = 0; t < T_STEPS; ++t) {
        float4 o;
        o.x = (msk[0] >> t & 1u) ? nt[0] : 0.0f;
        o.y = (msk[1] >> t & 1u) ? nt[1] : 0.0f;
        o.z = (msk[2] >> t & 1u) ? nt[2] : 0.0f;
        o.w = (msk[3] >> t & 1u) ? nt[3] : 0.0f;
        out[(size_t)t * (size_t)n4 + (size_t)i] = o;
    }
}

extern "C" void kernel_launch(void* const* d_in, const int* in_sizes, int n_in,
                              void* d_out, int out_size)
{
    const float* x      = (const float*)d_in[0];
    const float* thresh = (const float*)d_in[1];
    float* out          = (float*)d_out;

    // in_sizes[0] = T*N total elements; N = neurons per timestep.
    const long long total = in_sizes[0];
    const int n4 = (int)(total / T_STEPS / 4);   // float4 lanes per timestep

    const int threads = 256;
    const int blocks  = (n4 + threads - 1) / threads;
    newif_kernel<<<blocks, threads>>>(
        (const float4*)x, thresh, (float4*)out, n4);
}

// round 2
// speedup vs baseline: 1.0132x; 1.0132x over previous
#include <cuda_runtime.h>
#include <cstdint>

// newIF spiking neuron: T=8 timestep IF recurrence + compensation rescale.
// Purely HBM-bound: 256 MB in + 256 MB out, zero reuse.
// R2 changes vs R1 (83.5us, 6140 GB/s):
//  - __ldcs / __stcs streaming hints (evict-first; no reuse exists)
//  - 512-thread blocks to deepen per-SM outstanding-load queue (occ 63% -> ~75%)

static constexpr int T_STEPS = 8;

__global__ __launch_bounds__(512)
void newif_kernel(const float4* __restrict__ x,
                  const float*  __restrict__ thresh,
                  float4* __restrict__ out,
                  int n4)  // N/4 = number of float4 lanes per timestep
{
    int i = blockIdx.x * blockDim.x + threadIdx.x;
    if (i >= n4) return;

    const float thre      = __ldg(thresh);
    const float half_thre = 0.5f * thre;
    const float cap       = (float)T_STEPS * thre;

    // Front-batch all temporal loads: independent addresses -> MLP=8.
    float4 xv[T_STEPS];
#pragma unroll
    for (int t = 0; t < T_STEPS; ++t) {
        xv[t] = __ldcs(&x[(size_t)t * (size_t)n4 + (size_t)i]);
    }

    float mem[4];
    int   cnt[4];
    unsigned msk[4];
#pragma unroll
    for (int l = 0; l < 4; ++l) { mem[l] = half_thre; cnt[l] = 0; msk[l] = 0u; }

    // IF recurrence, spikes recorded as bits.
#pragma unroll
    for (int t = 0; t < T_STEPS; ++t) {
        const float* xt = reinterpret_cast<const float*>(&xv[t]);
#pragma unroll
        for (int l = 0; l < 4; ++l) {
            float m = mem[l] + xt[l];
            bool s = (m >= thre);          // zif(mem - thre): heaviside at 0
            if (s) { m -= thre; cnt[l]++; msk[l] |= (1u << t); }
            mem[l] = m;
        }
    }

    // Per-neuron effective threshold.
    float nt[4];
#pragma unroll
    for (int l = 0; l < 4; ++l) {
        float compen = mem[l] - half_thre + (float)cnt[l] * thre;
        compen = fminf(compen, cap);
        bool cond = (compen > 0.0f) && (cnt[l] > 0);
        nt[l] = cond ? (compen / (float)cnt[l]) : 0.0f;
    }

    // Rescale spikes and store (coalesced float4 per timestep, streaming).
#pragma unroll
    for (int t = 0; t < T_STEPS; ++t) {
        float4 o;
        o.x = (msk[0] >> t & 1u) ? nt[0] : 0.0f;
        o.y = (msk[1] >> t & 1u) ? nt[1] : 0.0f;
        o.z = (msk[2] >> t & 1u) ? nt[2] : 0.0f;
        o.w = (msk[3] >> t & 1u) ? nt[3] : 0.0f;
        __stcs(&out[(size_t)t * (size_t)n4 + (size_t)i], o);
    }
}

extern "C" void kernel_launch(void* const* d_in, const int* in_sizes, int n_in,
                              void* d_out, int out_size)
{
    const float* x      = (const float*)d_in[0];
    const float* thresh = (const float*)d_in[1];
    float* out          = (float*)d_out;

    const long long total = in_sizes[0];            // T*N elements
    const int n4 = (int)(total / T_STEPS / 4);      // float4 lanes per timestep

    const int threads = 512;
    const int blocks  = (n4 + threads - 1) / threads;
    newif_kernel<<<blocks, threads>>>(
        (const float4*)x, thresh, (float4*)out, n4);
}